// round 13
// baseline (speedup 1.0000x reference)
#include <cuda_runtime.h>
#include <cuda_bf16.h>
#include <cstdint>

#define BATCH 8

// ---------------- scratch ----------------
__device__ float g_bufA[8u*64u*128u*128u];
__device__ float g_bufB[8u*64u*128u*128u];
__device__ __nv_bfloat16 g_colH[18874368u];   // [k][n] hi plane (blocks 3-5 only; max L3: 2304x8192)
__device__ __nv_bfloat16 g_colL[18874368u];
__device__ __nv_bfloat16 g_wH[14710784u];
__device__ __nv_bfloat16 g_wL[14710784u];
__device__ float g_part[4194304u];
__device__ int4   g_tabI[196416];
__device__ float4 g_tabW[196416];
__device__ float g_vec1[8*4096];
__device__ float g_vec2[8*4096];

#define TB128 0
#define TB64  147456
#define TB32  184320
#define TB16  193536
#define TB8   195840

// ---------------- PTX helpers (family-common sm_80+) ----------------
__device__ __forceinline__ uint32_t s2u(const void* p) {
    uint32_t a;
    asm("{ .reg .u64 t; cvta.to.shared.u64 t, %1; cvt.u32.u64 %0, t; }" : "=r"(a) : "l"(p));
    return a;
}
#define CPA(dst, src) asm volatile("cp.async.cg.shared.global [%0], [%1], 16;" :: "r"(dst), "l"(src))
#define CPA_COMMIT()  asm volatile("cp.async.commit_group;" ::: "memory")
#define CPA_WAIT0()   asm volatile("cp.async.wait_group 0;" ::: "memory")
#define CPA_WAIT1()   asm volatile("cp.async.wait_group 1;" ::: "memory")
#define LDM4(r, addr) asm volatile("ldmatrix.sync.aligned.m8n8.x4.shared.b16 {%0,%1,%2,%3}, [%4];" \
    : "=r"((r)[0]), "=r"((r)[1]), "=r"((r)[2]), "=r"((r)[3]) : "r"(addr))
#define LDM4T(r, addr) asm volatile("ldmatrix.sync.aligned.m8n8.x4.trans.shared.b16 {%0,%1,%2,%3}, [%4];" \
    : "=r"((r)[0]), "=r"((r)[1]), "=r"((r)[2]), "=r"((r)[3]) : "r"(addr))
#define MMA(d, a, b) asm volatile( \
    "mma.sync.aligned.m16n8k16.row.col.f32.bf16.bf16.f32 {%0,%1,%2,%3},{%4,%5,%6,%7},{%8,%9},{%0,%1,%2,%3};" \
    : "+f"((d)[0]), "+f"((d)[1]), "+f"((d)[2]), "+f"((d)[3]) \
    : "r"((a)[0]), "r"((a)[1]), "r"((a)[2]), "r"((a)[3]), "r"((b)[0]), "r"((b)[1]))

// ---------------- tab build ----------------
__device__ __forceinline__ void tab_one(int t, int H, int base) {
    int HW = H * H;
    if (t >= HW * 9) return;
    int k = t % 9, pos = t / 9;
    int y = pos / H, x = pos % H;

    float cc = 0.5f * (float)H - 0.5f;
    float th = atan2f((float)x - cc, (float)y - cc);
    if (th < 0.f) th += 6.28318530717958647692f;
    th = rintf(th * 10000.0f) / 10000.0f;

    int ky = k / 3, kx = k % 3;
    float offy = 0.f, offx = 0.f;
    if (k != 4) {
        int m = (k < 4) ? k : k - 1;
        float ang = th + (float)(3.14159265358979323846 * 0.25 * (double)m);
        offy = cosf(ang) + (float)(1 - ky);
        offx = sinf(ang) + (float)(1 - kx);
    }
    float py = (float)(y - 1 + ky) + offy;
    float px = (float)(x - 1 + kx) + offx;
    float y0 = floorf(py), x0 = floorf(px);
    float fy = py - y0, fx = px - x0;
    float Hm = (float)(H - 1);

    float ys[2] = {y0, y0 + 1.f};
    float xs[2] = {x0, x0 + 1.f};
    float wy[2] = {1.f - fy, fy};
    float wx[2] = {1.f - fx, fx};

    int ids[4]; float ws[4]; int q = 0;
    #pragma unroll
    for (int iy = 0; iy < 2; iy++) {
        #pragma unroll
        for (int ix = 0; ix < 2; ix++) {
            float yf = ys[iy], xf = xs[ix];
            bool v = (yf >= 0.f) && (yf <= Hm) && (xf >= 0.f) && (xf <= Hm);
            int yi = (int)fminf(fmaxf(yf, 0.f), Hm);
            int xi = (int)fminf(fmaxf(xf, 0.f), Hm);
            ids[q] = yi * H + xi;
            ws[q]  = v ? (wy[iy] * wx[ix]) : 0.f;
            q++;
        }
    }
    g_tabI[base + t] = make_int4(ids[0], ids[1], ids[2], ids[3]);
    g_tabW[base + t] = make_float4(ws[0], ws[1], ws[2], ws[3]);
}

__global__ void prep_all() {
    int b = blockIdx.x, t = threadIdx.x;
    if      (b < 576) tab_one((b      ) * 256 + t, 128, TB128);
    else if (b < 720) tab_one((b - 576) * 256 + t,  64, TB64);
    else if (b < 756) tab_one((b - 720) * 256 + t,  32, TB32);
    else if (b < 765) tab_one((b - 756) * 256 + t,  16, TB16);
    else              tab_one((b - 765) * 256 + t,   8, TB8);
}

// ---------------- all-layer weight conversion ----------------
struct WParams {
    const float* W[13];
    int O[13]; int Kreal[13]; int Kpad[13]; unsigned off[13];
};
__global__ void convW_all(WParams P, __nv_bfloat16* __restrict__ wH, __nv_bfloat16* __restrict__ wL) {
    int layer = blockIdx.y;
    int Kr = P.Kreal[layer], Kp = P.Kpad[layer];
    int total = P.O[layer] * Kp;
    const float* W = P.W[layer];
    unsigned off = P.off[layer];
    for (int t = blockIdx.x * 256 + threadIdx.x; t < total; t += gridDim.x * 256) {
        int o = t / Kp, k = t - o * Kp;
        float w = (k < Kr) ? W[(size_t)o * Kr + k] : 0.f;
        __nv_bfloat16 h = __float2bfloat16(w);
        wH[off + t] = h;
        wL[off + t] = __float2bfloat16(w - __bfloat162float(h));
    }
}

// ---------------- FUSED deform-conv GEMM v3: 128n x 64o ----------------
// smem: tabI[9][128] int4 @0 (18432), tabW @18432, AH[32][136] @36864 (8704),
//       AL @45568, B 2 stages @54272 (each 10240: BH 5120, BL 5120). total 74752
#define FRSA 136
#define G_TABW 18432
#define G_AH   36864
#define G_AL   45568
#define G_B    54272
#define G_BSTG 10240
#define G_BL   5120
#define G_SMEM 74752
__global__ void __launch_bounds__(256, 2) conv_fused(
    const float* __restrict__ x, const __nv_bfloat16* __restrict__ WH,
    const __nv_bfloat16* __restrict__ WL, float* __restrict__ out,
    int Cin, int HW, int Kreal, int Kpad, int Cout, int tabBase) {
    extern __shared__ char smem[];
    uint32_t sb = s2u(smem);
    int tid = threadIdx.x, l = tid & 31, wid = tid >> 5;
    int wm = wid & 3, wn = wid >> 2;
    int bn = blockIdx.x * 128, bo = blockIdx.y * 64;
    int b0 = bn / HW, pos0 = bn % HW;      // HW % 128 == 0 -> no batch crossing
    const float* xb = x + (size_t)b0 * Cin * HW;
    int nch = Kpad >> 5;

    // stage offset tables: global is [pos][tap] (coalesced read), smem is [tap][pos]
    for (int e = tid; e < 1152; e += 256) {
        int pos = e / 9, tap = e - pos * 9;
        int4   id = g_tabI[tabBase + (pos0 + pos) * 9 + tap];
        float4 tw = g_tabW[tabBase + (pos0 + pos) * 9 + tap];
        *(int4*)(smem + (tap * 128 + pos) * 16) = id;
        *(float4*)(smem + G_TABW + (tap * 128 + pos) * 16) = tw;
    }

    float acc[2][4][4];
    #pragma unroll
    for (int i = 0; i < 2; i++)
        #pragma unroll
        for (int j = 0; j < 4; j++)
            #pragma unroll
            for (int q = 0; q < 4; q++) acc[i][j][q] = 0.f;

    // 1 position per lane: p = tid&127; half = tid>>7 covers 16 k-rows
    int p = tid & 127, half = tid >> 7;
    uint32_t hv[16], lv[16];

    auto gather = [&](int ch) {
        #pragma unroll
        for (int kk = 0; kk < 16; kk++) {
            int kg = ch * 32 + half * 16 + kk;
            hv[kk] = 0u; lv[kk] = 0u;
            if (kg < Kreal) {
                int c = kg / 9, tap = kg - c * 9;
                int4   id = *(const int4*)(smem + (tap * 128 + p) * 16);
                float4 tw = *(const float4*)(smem + G_TABW + (tap * 128 + p) * 16);
                const float* xc = xb + (size_t)c * HW;
                float v = xc[id.x] * tw.x + xc[id.y] * tw.y + xc[id.z] * tw.z + xc[id.w] * tw.w;
                __nv_bfloat16 h = __float2bfloat16(v);
                __nv_bfloat16 lo = __float2bfloat16(v - __bfloat162float(h));
                hv[kk] = (uint32_t)*(uint16_t*)&h;
                lv[kk] = (uint32_t)*(uint16_t*)&lo;
            }
        }
    };
    auto stsA = [&]() {
        #pragma unroll
        for (int kk = 0; kk < 16; kk++) {
            int krow = half * 16 + kk;
            uint16_t hh = (uint16_t)hv[kk], ll = (uint16_t)lv[kk];
            *(uint16_t*)(smem + G_AH + (krow * FRSA + p) * 2) = hh;
            *(uint16_t*)(smem + G_AL + (krow * FRSA + p) * 2) = ll;
        }
    };
    auto loadB = [&](int ch, int st) {
        int k0 = ch * 32;
        #pragma unroll
        for (int i = 0; i < 2; i++) {
            int u = tid + i * 256;
            int plane = u >> 8, rem = u & 255;
            int row = rem >> 2, c = rem & 3;
            const __nv_bfloat16* src = (plane ? WL : WH) + (size_t)(bo + row) * Kpad + k0 + c * 8;
            uint32_t dst = sb + G_B + st * G_BSTG + plane * G_BL + (uint32_t)(row * 40 + c * 8) * 2;
            CPA(dst, src);
        }
        CPA_COMMIT();
    };

    loadB(0, 0);
    __syncthreads();            // tab visible
    gather(0);
    stsA();

    int krow_l = (l & 7) + ((l & 16) >> 1);
    int mcol   = l & 8;
    int browB  = (l & 7) + ((l >> 4) << 3);
    int bcol   = ((l >> 3) & 1) * 8;

    for (int ch = 0; ch < nch; ch++) {
        if (ch + 1 < nch) { loadB(ch + 1, (ch + 1) & 1); CPA_WAIT1(); }
        else              { CPA_WAIT0(); }
        __syncthreads();        // A(ch) + B(ch) visible
        uint32_t bB = sb + G_B + (ch & 1) * G_BSTG;
        #pragma unroll
        for (int ks = 0; ks < 2; ks++) {
            uint32_t aH[2][4], aL[2][4], bH[4][2], bL[4][2];
            #pragma unroll
            for (int mi = 0; mi < 2; mi++) {
                uint32_t off = sb + G_AH + (uint32_t)((ks * 16 + krow_l) * FRSA + wm * 32 + mi * 16 + mcol) * 2;
                LDM4T(aH[mi], off);
                LDM4T(aL[mi], off + (G_AL - G_AH));
            }
            #pragma unroll
            for (int j = 0; j < 2; j++) {
                int row = wn * 32 + j * 16 + browB;
                uint32_t off = bB + (uint32_t)(row * 40 + ks * 16 + bcol) * 2;
                uint32_t r[4];
                LDM4(r, off);
                bH[2*j][0] = r[0]; bH[2*j][1] = r[1]; bH[2*j+1][0] = r[2]; bH[2*j+1][1] = r[3];
                LDM4(r, off + G_BL);
                bL[2*j][0] = r[0]; bL[2*j][1] = r[1]; bL[2*j+1][0] = r[2]; bL[2*j+1][1] = r[3];
            }
            #pragma unroll
            for (int mi = 0; mi < 2; mi++)
                #pragma unroll
                for (int nf = 0; nf < 4; nf++) {
                    MMA(acc[mi][nf], aH[mi], bH[nf]);
                    MMA(acc[mi][nf], aH[mi], bL[nf]);
                    MMA(acc[mi][nf], aL[mi], bH[nf]);
                }
        }
        if (ch + 1 < nch) {
            gather(ch + 1);     // overlaps other warps' MMA drain
            __syncthreads();    // all warps done reading A(ch)
            stsA();
        }
    }

    #pragma unroll
    for (int mi = 0; mi < 2; mi++)
        #pragma unroll
        for (int nf = 0; nf < 4; nf++) {
            int p0 = pos0 + wm * 32 + mi * 16 + (l >> 2);
            int col0 = bo + wn * 32 + nf * 8 + 2 * (l & 3);
            float* d = acc[mi][nf];
            float* op = out + ((size_t)b0 * Cout + col0) * HW;
            op[p0]          = fmaxf(d[0], 0.f);
            op[HW + p0]     = fmaxf(d[1], 0.f);
            op[p0 + 8]      = fmaxf(d[2], 0.f);
            op[HW + p0 + 8] = fmaxf(d[3], 0.f);
        }
}

// ---------------- materialized path (blocks 3-5) ----------------
__global__ void im2col2(const float* __restrict__ x, __nv_bfloat16* __restrict__ colH,
                        __nv_bfloat16* __restrict__ colL, int Cin, int HW, int Ntot,
                        int tabBase) {
    int n = blockIdx.x * blockDim.x + threadIdx.x;
    int tap = blockIdx.y;
    int pos = n % HW, b = n / HW;
    int4   id = g_tabI[tabBase + pos * 9 + tap];
    float4 w  = g_tabW[tabBase + pos * 9 + tap];
    const float* xb = x + (size_t)b * Cin * HW;
    size_t cstep = (size_t)9 * Ntot;
    __nv_bfloat16* pH = colH + (size_t)tap * Ntot + n;
    __nv_bfloat16* pL = colL + (size_t)tap * Ntot + n;
    for (int c = 0; c < Cin; c++) {
        const float* xc = xb + (size_t)c * HW;
        float v = xc[id.x] * w.x + xc[id.y] * w.y + xc[id.z] * w.z + xc[id.w] * w.w;
        __nv_bfloat16 h = __float2bfloat16(v);
        pH[c * cstep] = h;
        pL[c * cstep] = __float2bfloat16(v - __bfloat162float(h));
    }
}

#define RSA 264
#define RSB 40
#define OF_AL 16896
#define OF_B  33792
#define OF_BL 5120
#define STAGE_B 44032
#define SMEM_TOT 88064
__global__ void __launch_bounds__(256, 2) gemm_mma(
    const __nv_bfloat16* __restrict__ AH, const __nv_bfloat16* __restrict__ AL,
    const __nv_bfloat16* __restrict__ WH, const __nv_bfloat16* __restrict__ WL,
    float* __restrict__ out, float* __restrict__ part,
    int Ntot, int Kpad, int chunkK, int Cout, int HW) {
    extern __shared__ char smem[];
    uint32_t sb0 = s2u(smem);
    int tid = threadIdx.x, l = tid & 31, wid = tid >> 5;
    int wm = wid & 3, wn = wid >> 2;
    int bn = blockIdx.x * 256, bo = blockIdx.y * 64;
    int kStart = blockIdx.z * chunkK;
    int nk = chunkK >> 5;

    float acc[4][4][4];
    #pragma unroll
    for (int i = 0; i < 4; i++)
        #pragma unroll
        for (int j = 0; j < 4; j++)
            #pragma unroll
            for (int q = 0; q < 4; q++) acc[i][j][q] = 0.f;

    auto load_stage = [&](int st, int k0) {
        uint32_t sb = sb0 + st * STAGE_B;
        #pragma unroll
        for (int i = 0; i < 8; i++) {
            int u = tid + i * 256;
            int plane = u >> 10, rem = u & 1023;
            int krow = rem >> 5, c = rem & 31;
            const __nv_bfloat16* src = (plane ? AL : AH) + (size_t)(k0 + krow) * Ntot + bn + c * 8;
            uint32_t dst = sb + plane * OF_AL + (uint32_t)(krow * RSA + c * 8) * 2;
            CPA(dst, src);
        }
        #pragma unroll
        for (int i = 0; i < 2; i++) {
            int u = tid + i * 256;
            int plane = u >> 8, rem = u & 255;
            int row = rem >> 2, c = rem & 3;
            const __nv_bfloat16* src = (plane ? WL : WH) + (size_t)(bo + row) * Kpad + k0 + c * 8;
            uint32_t dst = sb + OF_B + plane * OF_BL + (uint32_t)(row * RSB + c * 8) * 2;
            CPA(dst, src);
        }
        CPA_COMMIT();
    };

    load_stage(0, kStart);

    int krow = (l & 7) + ((l & 16) >> 1);
    int mcol = (l & 8);
    int browB = (l & 7) + ((l >> 4) << 3);
    int bcol  = ((l >> 3) & 1) * 8;

    for (int it = 0; it < nk; it++) {
        CPA_WAIT0();
        __syncthreads();
        if (it + 1 < nk) load_stage((it + 1) & 1, kStart + (it + 1) * 32);

        uint32_t base = sb0 + (it & 1) * STAGE_B;
        #pragma unroll
        for (int ks = 0; ks < 2; ks++) {
            uint32_t aH[4][4], aL[4][4], bH[4][2], bL[4][2];
            #pragma unroll
            for (int mi = 0; mi < 4; mi++) {
                uint32_t off = (uint32_t)((ks * 16 + krow) * RSA + wm * 64 + mi * 16 + mcol) * 2;
                LDM4T(aH[mi], base + off);
                LDM4T(aL[mi], base + OF_AL + off);
            }
            #pragma unroll
            for (int j = 0; j < 2; j++) {
                int row = wn * 32 + j * 16 + browB;
                uint32_t off = OF_B + (uint32_t)(row * RSB + ks * 16 + bcol) * 2;
                uint32_t r[4];
                LDM4(r, base + off);
                bH[2*j][0] = r[0]; bH[2*j][1] = r[1]; bH[2*j+1][0] = r[2]; bH[2*j+1][1] = r[3];
                LDM4(r, base + off + OF_BL);
                bL[2*j][0] = r[0]; bL[2*j][1] = r[1]; bL[2*j+1][0] = r[2]; bL[2*j+1][1] = r[3];
            }
            #pragma unroll
            for (int mi = 0; mi < 4; mi++)
                #pragma unroll
                for (int nf = 0; nf < 4; nf++) {
                    MMA(acc[mi][nf], aH[mi], bH[nf]);
                    MMA(acc[mi][nf], aH[mi], bL[nf]);
                    MMA(acc[mi][nf], aL[mi], bH[nf]);
                }
        }
        __syncthreads();
    }

    bool dosplit = (gridDim.z > 1);
    #pragma unroll
    for (int mi = 0; mi < 4; mi++)
        #pragma unroll
        for (int nf = 0; nf < 4; nf++) {
            int row0 = bn + wm * 64 + mi * 16 + (l >> 2);
            int col0 = bo + wn * 32 + nf * 8 + 2 * (l & 3);
            float* d = acc[mi][nf];
            if (dosplit) {
                size_t zb = (size_t)blockIdx.z * Cout;
                part[(zb + col0)     * Ntot + row0]     = d[0];
                part[(zb + col0 + 1) * Ntot + row0]     = d[1];
                part[(zb + col0)     * Ntot + row0 + 8] = d[2];
                part[(zb + col0 + 1) * Ntot + row0 + 8] = d[3];
            } else {
                int b0 = row0 / HW, p0 = row0 % HW;
                int r1 = row0 + 8;
                int b1 = r1 / HW, p1 = r1 % HW;
                out[((size_t)b0 * Cout + col0)     * HW + p0] = fmaxf(d[0], 0.f);
                out[((size_t)b0 * Cout + col0 + 1) * HW + p0] = fmaxf(d[1], 0.f);
                out[((size_t)b1 * Cout + col0)     * HW + p1] = fmaxf(d[2], 0.f);
                out[((size_t)b1 * Cout + col0 + 1) * HW + p1] = fmaxf(d[3], 0.f);
            }
        }
}

__global__ void reduceK(const float* __restrict__ part, float* __restrict__ out,
                        int Cout, int N, int HW, int nslab) {
    int t = blockIdx.x * blockDim.x + threadIdx.x;
    if (t >= Cout * N) return;
    int o = t / N, n = t % N;
    float s = 0.f;
    for (int z = 0; z < nslab; z++)
        s += part[((size_t)z * Cout + o) * N + n];
    int b = n / HW, pos = n % HW;
    out[((size_t)b * Cout + o) * HW + pos] = fmaxf(s, 0.f);
}

// ---------------- pools / FC ----------------
__global__ void maxpool2(const float* __restrict__ in, float* __restrict__ out, int C, int H) {
    int Ho = H >> 1;
    int total = BATCH * C * Ho * Ho;
    int t = blockIdx.x * blockDim.x + threadIdx.x;
    if (t >= total) return;
    int xo = t % Ho;
    int tmp = t / Ho;
    int yo = tmp % Ho;
    int bc = tmp / Ho;
    const float* p = in + ((size_t)bc * H + 2 * yo) * H + 2 * xo;
    out[t] = fmaxf(fmaxf(p[0], p[1]), fmaxf(p[H], p[H + 1]));
}

__global__ void avgpool4(const float* __restrict__ in, float* __restrict__ out) {
    int t = blockIdx.x * blockDim.x + threadIdx.x;
    if (t >= BATCH * 512) return;
    const float* p = in + (size_t)t * 16;
    float s = 0.f;
    #pragma unroll
    for (int i = 0; i < 16; i++) s += p[i];
    out[t] = s * (1.f / 16.f);
}

__global__ void fc_kernel(const float* __restrict__ v, const float* __restrict__ Wf,
                          const float* __restrict__ bias, float* __restrict__ out,
                          int In, int Out, int doRelu) {
    int warp = (blockIdx.x * blockDim.x + threadIdx.x) >> 5;
    int lane = threadIdx.x & 31;
    if (warp >= Out) return;
    const float* wrow = Wf + (size_t)warp * In;
    float acc[BATCH];
    #pragma unroll
    for (int b = 0; b < BATCH; b++) acc[b] = 0.f;
    for (int i = lane; i < In; i += 32) {
        float wv = wrow[i];
        #pragma unroll
        for (int b = 0; b < BATCH; b++)
            acc[b] = fmaf(wv, v[b * In + i], acc[b]);
    }
    #pragma unroll
    for (int b = 0; b < BATCH; b++) {
        #pragma unroll
        for (int off = 16; off; off >>= 1)
            acc[b] += __shfl_xor_sync(0xffffffffu, acc[b], off);
    }
    if (lane == 0) {
        float bi = bias[warp];
        #pragma unroll
        for (int b = 0; b < BATCH; b++) {
            float r = acc[b] + bi;
            if (doRelu) r = fmaxf(r, 0.f);
            out[b * Out + warp] = r;
        }
    }
}

// ---------------- host ----------------
static const unsigned WOFF[13] = {0,2048,38912,112640,260096,555008,1144832,
                                  1734656,2914304,5273600,7632896,9992192,12351488};
static const int WO[13]  = {64,64,128,128,256,256,256,512,512,512,512,512,512};
static const int WKR[13] = {27,576,576,1152,1152,2304,2304,2304,4608,4608,4608,4608,4608};
static const int WKP[13] = {32,576,576,1152,1152,2304,2304,2304,4608,4608,4608,4608,4608};

struct Bufs {
    float *bufA, *bufB, *part, *vec1, *vec2;
    __nv_bfloat16 *colH, *colL, *wH, *wL;
};

static void conv_mat(const Bufs& B, const float* in, float* out, int li,
                     int Cin, int Cout, int H, int tabBase, int nsplit) {
    int HW = H * H;
    int Ntot = BATCH * HW;
    int Kpad = WKP[li];
    im2col2<<<dim3(Ntot / 256, 9), 256>>>(in, B.colH, B.colL, Cin, HW, Ntot, tabBase);
    dim3 gg(Ntot / 256, Cout / 64, nsplit);
    gemm_mma<<<gg, 256, SMEM_TOT>>>(B.colH, B.colL, B.wH + WOFF[li], B.wL + WOFF[li],
                                    out, B.part, Ntot, Kpad, Kpad / nsplit, Cout, HW);
    if (nsplit > 1)
        reduceK<<<(Cout * Ntot + 255) / 256, 256>>>(B.part, out, Cout, Ntot, HW, nsplit);
}

static void conv_fus(const Bufs& B, const float* in, float* out, int li,
                     int Cin, int Cout, int H, int tabBase) {
    int HW = H * H;
    int Ntot = BATCH * HW;
    dim3 gg(Ntot / 128, Cout / 64);
    conv_fused<<<gg, 256, G_SMEM>>>(in, B.wH + WOFF[li], B.wL + WOFF[li], out,
                                    Cin, HW, WKR[li], WKP[li], Cout, tabBase);
}

extern "C" void kernel_launch(void* const* d_in, const int* in_sizes, int n_in,
                              void* d_out, int out_size) {
    const float* x = (const float*)d_in[0];
    const float* fc1w = (const float*)d_in[14];
    const float* fc1b = (const float*)d_in[15];
    const float* fc2w = (const float*)d_in[16];
    const float* fc2b = (const float*)d_in[17];
    const float* fc3w = (const float*)d_in[18];
    const float* fc3b = (const float*)d_in[19];
    float* outp = (float*)d_out;

    Bufs B;
    cudaGetSymbolAddress((void**)&B.bufA, g_bufA);
    cudaGetSymbolAddress((void**)&B.bufB, g_bufB);
    cudaGetSymbolAddress((void**)&B.part, g_part);
    cudaGetSymbolAddress((void**)&B.vec1, g_vec1);
    cudaGetSymbolAddress((void**)&B.vec2, g_vec2);
    cudaGetSymbolAddress((void**)&B.colH, g_colH);
    cudaGetSymbolAddress((void**)&B.colL, g_colL);
    cudaGetSymbolAddress((void**)&B.wH,  g_wH);
    cudaGetSymbolAddress((void**)&B.wL,  g_wL);

    cudaFuncSetAttribute(gemm_mma, cudaFuncAttributeMaxDynamicSharedMemorySize, SMEM_TOT);
    cudaFuncSetAttribute(conv_fused, cudaFuncAttributeMaxDynamicSharedMemorySize, G_SMEM);

    WParams P;
    for (int i = 0; i < 13; i++) {
        P.W[i] = (const float*)d_in[1 + i];
        P.O[i] = WO[i]; P.Kreal[i] = WKR[i]; P.Kpad[i] = WKP[i]; P.off[i] = WOFF[i];
    }

    prep_all<<<768, 256>>>();                                    // 1
    convW_all<<<dim3(512, 13), 256>>>(P, B.wH, B.wL);            // 2
    conv_fus(B, x,      B.bufA, 0,  3,  64, 128, TB128);         // 3
    conv_fus(B, B.bufA, B.bufB, 1, 64,  64, 128, TB128);         // 4 <- profiled
    maxpool2<<<(BATCH*64*64*64 + 255) / 256, 256>>>(B.bufB, B.bufA, 64, 128);
    conv_fus(B, B.bufA, B.bufB, 2,  64, 128, 64, TB64);
    conv_fus(B, B.bufB, B.bufA, 3, 128, 128, 64, TB64);
    maxpool2<<<(BATCH*128*32*32 + 255) / 256, 256>>>(B.bufA, B.bufB, 128, 64);

    conv_mat(B, B.bufB, B.bufA, 4, 128, 256, 32, TB32, 2);
    conv_mat(B, B.bufA, B.bufB, 5, 256, 256, 32, TB32, 2);
    conv_mat(B, B.bufB, B.bufA, 6, 256, 256, 32, TB32, 2);
    maxpool2<<<(BATCH*256*16*16 + 255) / 256, 256>>>(B.bufA, B.bufB, 256, 32);

    conv_mat(B, B.bufB, B.bufA, 7, 256, 512, 16, TB16, 4);
    conv_mat(B, B.bufA, B.bufB, 8, 512, 512, 16, TB16, 4);
    conv_mat(B, B.bufB, B.bufA, 9, 512, 512, 16, TB16, 4);
    maxpool2<<<(BATCH*512*8*8 + 255) / 256, 256>>>(B.bufA, B.bufB, 512, 16);

    conv_mat(B, B.bufB, B.bufA, 10, 512, 512, 8, TB8, 16);
    conv_mat(B, B.bufA, B.bufB, 11, 512, 512, 8, TB8, 16);
    conv_mat(B, B.bufB, B.bufA, 12, 512, 512, 8, TB8, 16);
    maxpool2<<<(BATCH*512*4*4 + 255) / 256, 256>>>(B.bufA, B.bufB, 512, 8);

    avgpool4<<<(BATCH*512 + 255) / 256, 256>>>(B.bufB, B.vec1);
    fc_kernel<<<(4096*32 + 255) / 256, 256>>>(B.vec1, fc1w, fc1b, B.vec2, 512, 4096, 1);
    fc_kernel<<<(4096*32 + 255) / 256, 256>>>(B.vec2, fc2w, fc2b, B.vec1, 4096, 4096, 1);
    fc_kernel<<<(30*32 + 255) / 256, 256>>>(B.vec1, fc3w, fc3b, outp, 4096, 30, 0);
}

// round 14
// speedup vs baseline: 1.9724x; 1.9724x over previous
#include <cuda_runtime.h>
#include <cuda_bf16.h>
#include <cstdint>

#define BATCH 8

// ---------------- scratch ----------------
__device__ float g_bufA[8u*64u*128u*128u];
__device__ float g_bufB[8u*64u*128u*128u];
__device__ __nv_bfloat16 g_colH[75497472u];   // [k][n] hi plane (max conv1_2: 576 x 131072)
__device__ __nv_bfloat16 g_colL[75497472u];
__device__ __nv_bfloat16 g_wH[14710784u];
__device__ __nv_bfloat16 g_wL[14710784u];
__device__ float g_part[4194304u];
__device__ int4   g_tabI[196416];
__device__ float4 g_tabW[196416];
__device__ float g_vec1[8*4096];
__device__ float g_vec2[8*4096];

#define TB128 0
#define TB64  147456
#define TB32  184320
#define TB16  193536
#define TB8   195840

// ---------------- PTX helpers (family-common sm_80+) ----------------
__device__ __forceinline__ uint32_t s2u(const void* p) {
    uint32_t a;
    asm("{ .reg .u64 t; cvta.to.shared.u64 t, %1; cvt.u32.u64 %0, t; }" : "=r"(a) : "l"(p));
    return a;
}
#define CPA(dst, src) asm volatile("cp.async.cg.shared.global [%0], [%1], 16;" :: "r"(dst), "l"(src))
#define CPA_COMMIT()  asm volatile("cp.async.commit_group;" ::: "memory")
#define CPA_WAIT0()   asm volatile("cp.async.wait_group 0;" ::: "memory")
#define LDM4(r, addr) asm volatile("ldmatrix.sync.aligned.m8n8.x4.shared.b16 {%0,%1,%2,%3}, [%4];" \
    : "=r"((r)[0]), "=r"((r)[1]), "=r"((r)[2]), "=r"((r)[3]) : "r"(addr))
#define LDM4T(r, addr) asm volatile("ldmatrix.sync.aligned.m8n8.x4.trans.shared.b16 {%0,%1,%2,%3}, [%4];" \
    : "=r"((r)[0]), "=r"((r)[1]), "=r"((r)[2]), "=r"((r)[3]) : "r"(addr))
#define MMA(d, a, b) asm volatile( \
    "mma.sync.aligned.m16n8k16.row.col.f32.bf16.bf16.f32 {%0,%1,%2,%3},{%4,%5,%6,%7},{%8,%9},{%0,%1,%2,%3};" \
    : "+f"((d)[0]), "+f"((d)[1]), "+f"((d)[2]), "+f"((d)[3]) \
    : "r"((a)[0]), "r"((a)[1]), "r"((a)[2]), "r"((a)[3]), "r"((b)[0]), "r"((b)[1]))

// ---------------- tab build ----------------
__device__ __forceinline__ void tab_one(int t, int H, int base) {
    int HW = H * H;
    if (t >= HW * 9) return;
    int k = t % 9, pos = t / 9;
    int y = pos / H, x = pos % H;

    float cc = 0.5f * (float)H - 0.5f;
    float th = atan2f((float)x - cc, (float)y - cc);
    if (th < 0.f) th += 6.28318530717958647692f;
    th = rintf(th * 10000.0f) / 10000.0f;

    int ky = k / 3, kx = k % 3;
    float offy = 0.f, offx = 0.f;
    if (k != 4) {
        int m = (k < 4) ? k : k - 1;
        float ang = th + (float)(3.14159265358979323846 * 0.25 * (double)m);
        offy = cosf(ang) + (float)(1 - ky);
        offx = sinf(ang) + (float)(1 - kx);
    }
    float py = (float)(y - 1 + ky) + offy;
    float px = (float)(x - 1 + kx) + offx;
    float y0 = floorf(py), x0 = floorf(px);
    float fy = py - y0, fx = px - x0;
    float Hm = (float)(H - 1);

    float ys[2] = {y0, y0 + 1.f};
    float xs[2] = {x0, x0 + 1.f};
    float wy[2] = {1.f - fy, fy};
    float wx[2] = {1.f - fx, fx};

    int ids[4]; float ws[4]; int q = 0;
    #pragma unroll
    for (int iy = 0; iy < 2; iy++) {
        #pragma unroll
        for (int ix = 0; ix < 2; ix++) {
            float yf = ys[iy], xf = xs[ix];
            bool v = (yf >= 0.f) && (yf <= Hm) && (xf >= 0.f) && (xf <= Hm);
            int yi = (int)fminf(fmaxf(yf, 0.f), Hm);
            int xi = (int)fminf(fmaxf(xf, 0.f), Hm);
            ids[q] = yi * H + xi;
            ws[q]  = v ? (wy[iy] * wx[ix]) : 0.f;
            q++;
        }
    }
    g_tabI[base + t] = make_int4(ids[0], ids[1], ids[2], ids[3]);
    g_tabW[base + t] = make_float4(ws[0], ws[1], ws[2], ws[3]);
}

__global__ void prep_all() {
    int b = blockIdx.x, t = threadIdx.x;
    if      (b < 576) tab_one((b      ) * 256 + t, 128, TB128);
    else if (b < 720) tab_one((b - 576) * 256 + t,  64, TB64);
    else if (b < 756) tab_one((b - 720) * 256 + t,  32, TB32);
    else if (b < 765) tab_one((b - 756) * 256 + t,  16, TB16);
    else              tab_one((b - 765) * 256 + t,   8, TB8);
}

// ---------------- all-layer weight conversion ----------------
struct WParams {
    const float* W[13];
    int O[13]; int Kreal[13]; int Kpad[13]; unsigned off[13];
};
__global__ void convW_all(WParams P, __nv_bfloat16* __restrict__ wH, __nv_bfloat16* __restrict__ wL) {
    int layer = blockIdx.y;
    int Kr = P.Kreal[layer], Kp = P.Kpad[layer];
    int total = P.O[layer] * Kp;
    const float* W = P.W[layer];
    unsigned off = P.off[layer];
    for (int t = blockIdx.x * 256 + threadIdx.x; t < total; t += gridDim.x * 256) {
        int o = t / Kp, k = t - o * Kp;
        float w = (k < Kr) ? W[(size_t)o * Kr + k] : 0.f;
        __nv_bfloat16 h = __float2bfloat16(w);
        wH[off + t] = h;
        wL[off + t] = __float2bfloat16(w - __bfloat162float(h));
    }
}

// ---------------- deformable im2col -> bf16 hi/lo, [k][n], channel-parallel ----------------
// grid: (Ntot/256, 9, Cin/CB); thread handles CB channels for one (n, tap)
__global__ void im2col2(const float* __restrict__ x, __nv_bfloat16* __restrict__ colH,
                        __nv_bfloat16* __restrict__ colL, int Cin, int HW, int Ntot,
                        int tabBase, int CB) {
    int n = blockIdx.x * blockDim.x + threadIdx.x;
    int tap = blockIdx.y;
    int c0 = blockIdx.z * CB;
    int pos = n % HW, b = n / HW;
    int4   id = g_tabI[tabBase + pos * 9 + tap];
    float4 w  = g_tabW[tabBase + pos * 9 + tap];
    const float* xb = x + ((size_t)b * Cin + c0) * HW;
    size_t cstep = (size_t)9 * Ntot;
    __nv_bfloat16* pH = colH + ((size_t)c0 * 9 + tap) * Ntot + n;
    __nv_bfloat16* pL = colL + ((size_t)c0 * 9 + tap) * Ntot + n;
    for (int c = 0; c < CB; c++) {
        const float* xc = xb + (size_t)c * HW;
        float v = xc[id.x] * w.x + xc[id.y] * w.y + xc[id.z] * w.z + xc[id.w] * w.w;
        __nv_bfloat16 h = __float2bfloat16(v);
        pH[c * cstep] = h;
        pL[c * cstep] = __float2bfloat16(v - __bfloat162float(h));
    }
}

// ---------------- HMMA GEMM 256x64x32, 2 CTAs/SM ----------------
#define RSA 264
#define RSB 40
#define OF_AL 16896
#define OF_B  33792
#define OF_BL 5120
#define STAGE_B 44032
#define SMEM_TOT 88064
__global__ void __launch_bounds__(256, 2) gemm_mma(
    const __nv_bfloat16* __restrict__ AH, const __nv_bfloat16* __restrict__ AL,
    const __nv_bfloat16* __restrict__ WH, const __nv_bfloat16* __restrict__ WL,
    float* __restrict__ out, float* __restrict__ part,
    int Ntot, int Kpad, int chunkK, int Cout, int HW) {
    extern __shared__ char smem[];
    uint32_t sb0 = s2u(smem);
    int tid = threadIdx.x, l = tid & 31, wid = tid >> 5;
    int wm = wid & 3, wn = wid >> 2;
    int bn = blockIdx.x * 256, bo = blockIdx.y * 64;
    int kStart = blockIdx.z * chunkK;
    int nk = chunkK >> 5;

    float acc[4][4][4];
    #pragma unroll
    for (int i = 0; i < 4; i++)
        #pragma unroll
        for (int j = 0; j < 4; j++)
            #pragma unroll
            for (int q = 0; q < 4; q++) acc[i][j][q] = 0.f;

    auto load_stage = [&](int st, int k0) {
        uint32_t sb = sb0 + st * STAGE_B;
        #pragma unroll
        for (int i = 0; i < 8; i++) {
            int u = tid + i * 256;
            int plane = u >> 10, rem = u & 1023;
            int krow = rem >> 5, c = rem & 31;
            const __nv_bfloat16* src = (plane ? AL : AH) + (size_t)(k0 + krow) * Ntot + bn + c * 8;
            uint32_t dst = sb + plane * OF_AL + (uint32_t)(krow * RSA + c * 8) * 2;
            CPA(dst, src);
        }
        #pragma unroll
        for (int i = 0; i < 2; i++) {
            int u = tid + i * 256;
            int plane = u >> 8, rem = u & 255;
            int row = rem >> 2, c = rem & 3;
            const __nv_bfloat16* src = (plane ? WL : WH) + (size_t)(bo + row) * Kpad + k0 + c * 8;
            uint32_t dst = sb + OF_B + plane * OF_BL + (uint32_t)(row * RSB + c * 8) * 2;
            CPA(dst, src);
        }
        CPA_COMMIT();
    };

    load_stage(0, kStart);

    int krow = (l & 7) + ((l & 16) >> 1);
    int mcol = (l & 8);
    int browB = (l & 7) + ((l >> 4) << 3);
    int bcol  = ((l >> 3) & 1) * 8;

    for (int it = 0; it < nk; it++) {
        CPA_WAIT0();
        __syncthreads();
        if (it + 1 < nk) load_stage((it + 1) & 1, kStart + (it + 1) * 32);

        uint32_t base = sb0 + (it & 1) * STAGE_B;
        #pragma unroll
        for (int ks = 0; ks < 2; ks++) {
            uint32_t aH[4][4], aL[4][4], bH[4][2], bL[4][2];
            #pragma unroll
            for (int mi = 0; mi < 4; mi++) {
                uint32_t off = (uint32_t)((ks * 16 + krow) * RSA + wm * 64 + mi * 16 + mcol) * 2;
                LDM4T(aH[mi], base + off);
                LDM4T(aL[mi], base + OF_AL + off);
            }
            #pragma unroll
            for (int j = 0; j < 2; j++) {
                int row = wn * 32 + j * 16 + browB;
                uint32_t off = OF_B + (uint32_t)(row * RSB + ks * 16 + bcol) * 2;
                uint32_t r[4];
                LDM4(r, base + off);
                bH[2*j][0] = r[0]; bH[2*j][1] = r[1]; bH[2*j+1][0] = r[2]; bH[2*j+1][1] = r[3];
                LDM4(r, base + off + OF_BL);
                bL[2*j][0] = r[0]; bL[2*j][1] = r[1]; bL[2*j+1][0] = r[2]; bL[2*j+1][1] = r[3];
            }
            #pragma unroll
            for (int mi = 0; mi < 4; mi++)
                #pragma unroll
                for (int nf = 0; nf < 4; nf++) {
                    MMA(acc[mi][nf], aH[mi], bH[nf]);
                    MMA(acc[mi][nf], aH[mi], bL[nf]);
                    MMA(acc[mi][nf], aL[mi], bH[nf]);
                }
        }
        __syncthreads();
    }

    bool dosplit = (gridDim.z > 1);
    #pragma unroll
    for (int mi = 0; mi < 4; mi++)
        #pragma unroll
        for (int nf = 0; nf < 4; nf++) {
            int row0 = bn + wm * 64 + mi * 16 + (l >> 2);
            int col0 = bo + wn * 32 + nf * 8 + 2 * (l & 3);
            float* d = acc[mi][nf];
            if (dosplit) {
                size_t zb = (size_t)blockIdx.z * Cout;
                part[(zb + col0)     * Ntot + row0]     = d[0];
                part[(zb + col0 + 1) * Ntot + row0]     = d[1];
                part[(zb + col0)     * Ntot + row0 + 8] = d[2];
                part[(zb + col0 + 1) * Ntot + row0 + 8] = d[3];
            } else {
                int b0 = row0 / HW, p0 = row0 % HW;
                int r1 = row0 + 8;
                int b1 = r1 / HW, p1 = r1 % HW;
                out[((size_t)b0 * Cout + col0)     * HW + p0] = fmaxf(d[0], 0.f);
                out[((size_t)b0 * Cout + col0 + 1) * HW + p0] = fmaxf(d[1], 0.f);
                out[((size_t)b1 * Cout + col0)     * HW + p1] = fmaxf(d[2], 0.f);
                out[((size_t)b1 * Cout + col0 + 1) * HW + p1] = fmaxf(d[3], 0.f);
            }
        }
}

__global__ void reduceK(const float* __restrict__ part, float* __restrict__ out,
                        int Cout, int N, int HW, int nslab) {
    int t = blockIdx.x * blockDim.x + threadIdx.x;
    if (t >= Cout * N) return;
    int o = t / N, n = t % N;
    float s = 0.f;
    for (int z = 0; z < nslab; z++)
        s += part[((size_t)z * Cout + o) * N + n];
    int b = n / HW, pos = n % HW;
    out[((size_t)b * Cout + o) * HW + pos] = fmaxf(s, 0.f);
}

// ---------------- pools / FC ----------------
__global__ void maxpool2(const float* __restrict__ in, float* __restrict__ out, int C, int H) {
    int Ho = H >> 1;
    int total = BATCH * C * Ho * Ho;
    int t = blockIdx.x * blockDim.x + threadIdx.x;
    if (t >= total) return;
    int xo = t % Ho;
    int tmp = t / Ho;
    int yo = tmp % Ho;
    int bc = tmp / Ho;
    const float* p = in + ((size_t)bc * H + 2 * yo) * H + 2 * xo;
    out[t] = fmaxf(fmaxf(p[0], p[1]), fmaxf(p[H], p[H + 1]));
}

__global__ void avgpool4(const float* __restrict__ in, float* __restrict__ out) {
    int t = blockIdx.x * blockDim.x + threadIdx.x;
    if (t >= BATCH * 512) return;
    const float* p = in + (size_t)t * 16;
    float s = 0.f;
    #pragma unroll
    for (int i = 0; i < 16; i++) s += p[i];
    out[t] = s * (1.f / 16.f);
}

__global__ void fc_kernel(const float* __restrict__ v, const float* __restrict__ Wf,
                          const float* __restrict__ bias, float* __restrict__ out,
                          int In, int Out, int doRelu) {
    int warp = (blockIdx.x * blockDim.x + threadIdx.x) >> 5;
    int lane = threadIdx.x & 31;
    if (warp >= Out) return;
    const float* wrow = Wf + (size_t)warp * In;
    float acc[BATCH];
    #pragma unroll
    for (int b = 0; b < BATCH; b++) acc[b] = 0.f;
    for (int i = lane; i < In; i += 32) {
        float wv = wrow[i];
        #pragma unroll
        for (int b = 0; b < BATCH; b++)
            acc[b] = fmaf(wv, v[b * In + i], acc[b]);
    }
    #pragma unroll
    for (int b = 0; b < BATCH; b++) {
        #pragma unroll
        for (int off = 16; off; off >>= 1)
            acc[b] += __shfl_xor_sync(0xffffffffu, acc[b], off);
    }
    if (lane == 0) {
        float bi = bias[warp];
        #pragma unroll
        for (int b = 0; b < BATCH; b++) {
            float r = acc[b] + bi;
            if (doRelu) r = fmaxf(r, 0.f);
            out[b * Out + warp] = r;
        }
    }
}

// ---------------- host ----------------
static const unsigned WOFF[13] = {0,2048,38912,112640,260096,555008,1144832,
                                  1734656,2914304,5273600,7632896,9992192,12351488};
static const int WO[13]  = {64,64,128,128,256,256,256,512,512,512,512,512,512};
static const int WKR[13] = {27,576,576,1152,1152,2304,2304,2304,4608,4608,4608,4608,4608};
static const int WKP[13] = {32,576,576,1152,1152,2304,2304,2304,4608,4608,4608,4608,4608};

struct Bufs {
    float *bufA, *bufB, *part, *vec1, *vec2;
    __nv_bfloat16 *colH, *colL, *wH, *wL;
};

static void conv_mat(const Bufs& B, const float* in, float* out, int li,
                     int Cin, int Cout, int H, int tabBase, int nsplit) {
    int HW = H * H;
    int Ntot = BATCH * HW;
    int Kpad = WKP[li];
    // channel-parallel im2col: pick CB so the grid has >= ~1000 CTAs
    int CB = Cin;
    while (CB > 1 && (Ntot / 256) * 9 * (Cin / CB) < 1024 && (CB & 1) == 0)
        CB >>= 1;
    if (CB > 16 && Ntot <= 8192) CB = 16;   // cap serial loop for mid layers
    dim3 gi(Ntot / 256, 9, Cin / CB);
    im2col2<<<gi, 256>>>(in, B.colH, B.colL, Cin, HW, Ntot, tabBase, CB);
    dim3 gg(Ntot / 256, Cout / 64, nsplit);
    gemm_mma<<<gg, 256, SMEM_TOT>>>(B.colH, B.colL, B.wH + WOFF[li], B.wL + WOFF[li],
                                    out, B.part, Ntot, Kpad, Kpad / nsplit, Cout, HW);
    if (nsplit > 1)
        reduceK<<<(Cout * Ntot + 255) / 256, 256>>>(B.part, out, Cout, Ntot, HW, nsplit);
}

extern "C" void kernel_launch(void* const* d_in, const int* in_sizes, int n_in,
                              void* d_out, int out_size) {
    const float* x = (const float*)d_in[0];
    const float* fc1w = (const float*)d_in[14];
    const float* fc1b = (const float*)d_in[15];
    const float* fc2w = (const float*)d_in[16];
    const float* fc2b = (const float*)d_in[17];
    const float* fc3w = (const float*)d_in[18];
    const float* fc3b = (const float*)d_in[19];
    float* outp = (float*)d_out;

    Bufs B;
    cudaGetSymbolAddress((void**)&B.bufA, g_bufA);
    cudaGetSymbolAddress((void**)&B.bufB, g_bufB);
    cudaGetSymbolAddress((void**)&B.part, g_part);
    cudaGetSymbolAddress((void**)&B.vec1, g_vec1);
    cudaGetSymbolAddress((void**)&B.vec2, g_vec2);
    cudaGetSymbolAddress((void**)&B.colH, g_colH);
    cudaGetSymbolAddress((void**)&B.colL, g_colL);
    cudaGetSymbolAddress((void**)&B.wH,  g_wH);
    cudaGetSymbolAddress((void**)&B.wL,  g_wL);

    cudaFuncSetAttribute(gemm_mma, cudaFuncAttributeMaxDynamicSharedMemorySize, SMEM_TOT);

    WParams P;
    for (int i = 0; i < 13; i++) {
        P.W[i] = (const float*)d_in[1 + i];
        P.O[i] = WO[i]; P.Kreal[i] = WKR[i]; P.Kpad[i] = WKP[i]; P.off[i] = WOFF[i];
    }

    prep_all<<<768, 256>>>();
    convW_all<<<dim3(512, 13), 256>>>(P, B.wH, B.wL);

    conv_mat(B, x,      B.bufA, 0,  3,  64, 128, TB128, 1);
    conv_mat(B, B.bufA, B.bufB, 1, 64,  64, 128, TB128, 1);
    maxpool2<<<(BATCH*64*64*64 + 255) / 256, 256>>>(B.bufB, B.bufA, 64, 128);

    conv_mat(B, B.bufA, B.bufB, 2,  64, 128, 64, TB64, 1);
    conv_mat(B, B.bufB, B.bufA, 3, 128, 128, 64, TB64, 1);
    maxpool2<<<(BATCH*128*32*32 + 255) / 256, 256>>>(B.bufA, B.bufB, 128, 64);

    conv_mat(B, B.bufB, B.bufA, 4, 128, 256, 32, TB32, 2);
    conv_mat(B, B.bufA, B.bufB, 5, 256, 256, 32, TB32, 2);
    conv_mat(B, B.bufB, B.bufA, 6, 256, 256, 32, TB32, 2);
    maxpool2<<<(BATCH*256*16*16 + 255) / 256, 256>>>(B.bufA, B.bufB, 256, 32);

    conv_mat(B, B.bufB, B.bufA, 7, 256, 512, 16, TB16, 4);
    conv_mat(B, B.bufA, B.bufB, 8, 512, 512, 16, TB16, 4);
    conv_mat(B, B.bufB, B.bufA, 9, 512, 512, 16, TB16, 4);
    maxpool2<<<(BATCH*512*8*8 + 255) / 256, 256>>>(B.bufA, B.bufB, 512, 16);

    conv_mat(B, B.bufB, B.bufA, 10, 512, 512, 8, TB8, 16);
    conv_mat(B, B.bufA, B.bufB, 11, 512, 512, 8, TB8, 16);
    conv_mat(B, B.bufB, B.bufA, 12, 512, 512, 8, TB8, 16);
    maxpool2<<<(BATCH*512*4*4 + 255) / 256, 256>>>(B.bufA, B.bufB, 512, 8);

    avgpool4<<<(BATCH*512 + 255) / 256, 256>>>(B.bufB, B.vec1);
    fc_kernel<<<(4096*32 + 255) / 256, 256>>>(B.vec1, fc1w, fc1b, B.vec2, 512, 4096, 1);
    fc_kernel<<<(4096*32 + 255) / 256, 256>>>(B.vec2, fc2w, fc2b, B.vec1, 4096, 4096, 1);
    fc_kernel<<<(30*32 + 255) / 256, 256>>>(B.vec1, fc3w, fc3b, outp, 4096, 30, 0);
}